// round 4
// baseline (speedup 1.0000x reference)
#include <cuda_runtime.h>
#include <cstdint>

#define DD 8
#define BB 8
#define NN 2048
#define NN2 (NN * NN)        // 4194304
#define NQ  (NN2 / 4)        // 1048576 quads

// 64-bit spike mask per presynaptic neuron e: bit (d*8 + b) set iff Xd[d,b,e]==1
__device__ unsigned long long g_spike[NN];
// Gate byte per synapse (e,o): bit b set iff Xd[didx(e,o), b, e]==1. Packed 4/word.
__device__ unsigned int g_gate[NQ];   // 4 MB static scratch

// ---------------------------------------------------------------------------
// Kernel 1: pack spikes (1 thread per e, coalesced, no atomics) + zero out
// ---------------------------------------------------------------------------
__global__ void __launch_bounds__(256)
pack_kernel(const float* __restrict__ Xd, float* __restrict__ out) {
    const int e = blockIdx.x * blockDim.x + threadIdx.x;   // 0..NN-1
    if (e >= NN) return;
    unsigned long long m = 0;
#pragma unroll
    for (int db = 0; db < DD * BB; db++) {
        if (Xd[(size_t)db * NN + e] > 0.5f) m |= (1ull << db);
    }
    g_spike[e] = m;
#pragma unroll
    for (int k = 0; k < BB; k++) out[k * NN + e] = 0.0f;
}

// ---------------------------------------------------------------------------
// Kernel 2: stream delaymap -> gate bytes. d=0 stream never read
// (it contributes 0 to the one-hot dot product). Pure streaming, 4096 CTAs.
// ---------------------------------------------------------------------------
__global__ void __launch_bounds__(256)
gate_kernel(const float4* __restrict__ dm4) {
    int i = blockIdx.x * blockDim.x + threadIdx.x;  // quad index over N*N/4
    if (i >= NQ) return;
    const int e = i / (NN / 4);                     // warp-uniform row

    float fx = 0.f, fy = 0.f, fz = 0.f, fw = 0.f;
#pragma unroll
    for (int d = 1; d < DD; d++) {
        float4 v = dm4[(size_t)d * NQ + i];
        const float fd = (float)d;
        fx = fmaf(v.x, fd, fx);
        fy = fmaf(v.y, fd, fy);
        fz = fmaf(v.z, fd, fz);
        fw = fmaf(v.w, fd, fw);
    }
    const unsigned long long bits = g_spike[e];
    unsigned b0 = (unsigned)(bits >> (((int)fx) * 8)) & 0xFFu;
    unsigned b1 = (unsigned)(bits >> (((int)fy) * 8)) & 0xFFu;
    unsigned b2 = (unsigned)(bits >> (((int)fz) * 8)) & 0xFFu;
    unsigned b3 = (unsigned)(bits >> (((int)fw) * 8)) & 0xFFu;
    g_gate[i] = b0 | (b1 << 8) | (b2 << 16) | (b3 << 24);
}

// ---------------------------------------------------------------------------
// Kernel 3: gated blend + reduce. Branch-free: gates prefetched, statics
// unconditional streams, Wlong via predicated loads. 1024 CTAs.
// ---------------------------------------------------------------------------
#define ESPLIT 128
#define ECHUNK (NN / ESPLIT)   // 16

__global__ void __launch_bounds__(256)
reduce_kernel(const float* __restrict__ W,     // (N,N)
              const float* __restrict__ Wl,    // Wlong (B,N,N)
              const float* __restrict__ F,     // STDP_frac (N,N)
              const float* __restrict__ S,     // signs (N,N)
              float* __restrict__ out)         // (B,N)
{
    const int o     = blockIdx.x * blockDim.x + threadIdx.x;
    const int ebase = blockIdx.y * ECHUNK;
    const unsigned char* __restrict__ gb8 = (const unsigned char*)g_gate;

    // Prefetch all gate bytes for the chunk (independent loads, mostly L2-hit)
    unsigned gb[ECHUNK];
#pragma unroll
    for (int ee = 0; ee < ECHUNK; ee++) {
        gb[ee] = gb8[(size_t)(ebase + ee) * NN + o];
    }

    float acc[BB];
#pragma unroll
    for (int b = 0; b < BB; b++) acc[b] = 0.0f;

#pragma unroll 4
    for (int ee = 0; ee < ECHUNK; ee++) {
        const size_t eo = (size_t)(ebase + ee) * NN + o;
        // Unconditional streaming of static coefficients (sector use ~96%)
        const float s = S[eo];
        const float w = W[eo];
        const float f = F[eo];
        const float cs = s * w * (1.0f - f);   // static part
        const float cp = s * f;                // plastic multiplier

        const unsigned g  = gb[ee];
        const float* wlp = Wl + eo;
#pragma unroll
        for (int b = 0; b < BB; b++) {
            const bool on = (g >> b) & 1u;
            const float wl = on ? wlp[(size_t)b * NN2] : 0.0f;  // @P LDG
            acc[b] += on ? fmaf(cp, wl, cs) : 0.0f;
        }
    }

#pragma unroll
    for (int b = 0; b < BB; b++) {
        atomicAdd(&out[b * NN + o], acc[b]);
    }
}

// ---------------------------------------------------------------------------
// Launch
// ---------------------------------------------------------------------------
extern "C" void kernel_launch(void* const* d_in, const int* in_sizes, int n_in,
                              void* d_out, int out_size) {
    const float* Xd = (const float*)d_in[0];   // (D,B,N)
    const float* dm = (const float*)d_in[1];   // (D,N,N)
    const float* W  = (const float*)d_in[2];   // (N,N)
    const float* Wl = (const float*)d_in[3];   // (B,N,N)
    const float* F  = (const float*)d_in[4];   // (N,N)
    const float* S  = (const float*)d_in[5];   // (N,N)
    float* out = (float*)d_out;                // (B,N)

    pack_kernel<<<NN / 256, 256>>>(Xd, out);
    gate_kernel<<<NQ / 256, 256>>>((const float4*)dm);

    dim3 grid(NN / 256, ESPLIT);
    reduce_kernel<<<grid, 256>>>(W, Wl, F, S, out);
}

// round 5
// speedup vs baseline: 1.0216x; 1.0216x over previous
#include <cuda_runtime.h>
#include <cstdint>

#define DD 8
#define BB 8
#define NN 2048
#define NN2 (NN * NN)        // 4194304
#define NQ  (NN2 / 4)        // 1048576 quads

// 64-bit spike mask per presynaptic neuron e: bit (d*8 + b) set iff Xd[d,b,e]==1
__device__ unsigned long long g_spike[NN];
// Gate byte per synapse (e,o): bit b set iff Xd[didx(e,o), b, e]==1. Packed 4/word.
__device__ unsigned int g_gate[NQ];   // 4 MB static scratch

// ---------------------------------------------------------------------------
// Kernel 1: zero spikes+out, then pack Xd via atomicOr (proven-fast form).
// Thread i < NN zeroes g_spike[i]; i < B*N zeroes out. All threads pack.
// Launched as two kernels to keep ordering simple & cheap.
// ---------------------------------------------------------------------------
__global__ void __launch_bounds__(256)
zero_kernel(float* __restrict__ out) {
    int i = blockIdx.x * blockDim.x + threadIdx.x;
    if (i < BB * NN) out[i] = 0.0f;
    if (i < NN) g_spike[i] = 0ull;
}

__global__ void __launch_bounds__(256)
pack_kernel(const float* __restrict__ Xd) {
    int i = blockIdx.x * blockDim.x + threadIdx.x;  // over D*B*N
    if (i >= DD * BB * NN) return;
    if (Xd[i] > 0.5f) {
        int e  = i % NN;
        int db = i / NN;             // bit index = d*B + b
        atomicOr(&g_spike[e], 1ull << db);
    }
}

// ---------------------------------------------------------------------------
// Kernel 2: stream delaymap -> gate bytes. d=0 plane never read (contributes
// 0 to the one-hot dot product). Pure streaming, 4096 CTAs.
// ---------------------------------------------------------------------------
__global__ void __launch_bounds__(256)
gate_kernel(const float4* __restrict__ dm4) {
    int i = blockIdx.x * blockDim.x + threadIdx.x;  // quad index over N*N/4
    if (i >= NQ) return;
    const int e = i / (NN / 4);                     // warp-uniform row

    float fx = 0.f, fy = 0.f, fz = 0.f, fw = 0.f;
#pragma unroll
    for (int d = 1; d < DD; d++) {
        float4 v = dm4[(size_t)d * NQ + i];
        const float fd = (float)d;
        fx = fmaf(v.x, fd, fx);
        fy = fmaf(v.y, fd, fy);
        fz = fmaf(v.z, fd, fz);
        fw = fmaf(v.w, fd, fw);
    }
    const unsigned long long bits = g_spike[e];
    unsigned b0 = (unsigned)(bits >> (((int)fx) * 8)) & 0xFFu;
    unsigned b1 = (unsigned)(bits >> (((int)fy) * 8)) & 0xFFu;
    unsigned b2 = (unsigned)(bits >> (((int)fz) * 8)) & 0xFFu;
    unsigned b3 = (unsigned)(bits >> (((int)fw) * 8)) & 0xFFu;
    g_gate[i] = b0 | (b1 << 8) | (b2 << 16) | (b3 << 24);
}

// ---------------------------------------------------------------------------
// Kernel 3: gated blend + reduce. R3's branchy structure, vectorized over
// pairs of o. thread -> (o, o+1); block.y -> chunk of e. 1024 CTAs.
// ---------------------------------------------------------------------------
#define ESPLIT 256
#define ECHUNK (NN / ESPLIT)   // 8

__global__ void __launch_bounds__(256)
reduce_kernel(const float2* __restrict__ W2,    // (N,N)
              const float2* __restrict__ Wl2,   // Wlong (B,N,N)
              const float2* __restrict__ F2,    // STDP_frac (N,N)
              const float2* __restrict__ S2,    // signs (N,N)
              float* __restrict__ out)          // (B,N)
{
    const int o2    = blockIdx.x * blockDim.x + threadIdx.x;  // pair index
    const int o     = o2 * 2;
    const int ebase = blockIdx.y * ECHUNK;
    const unsigned short* __restrict__ gb16 = (const unsigned short*)g_gate;

    float acc0[BB], acc1[BB];
#pragma unroll
    for (int b = 0; b < BB; b++) { acc0[b] = 0.0f; acc1[b] = 0.0f; }

#pragma unroll
    for (int ee = 0; ee < ECHUNK; ee++) {
        const int e = ebase + ee;
        const size_t idx2 = (size_t)e * (NN / 2) + o2;  // float2/ushort index
        const unsigned g = gb16[idx2];                  // gates for o (low byte), o+1 (high)
        if (g == 0) continue;

        const float2 s = S2[idx2];
        const float2 w = W2[idx2];
        const float2 f = F2[idx2];
        const float cs0 = s.x * w.x * (1.0f - f.x);
        const float cp0 = s.x * f.x;
        const float cs1 = s.y * w.y * (1.0f - f.y);
        const float cp1 = s.y * f.y;

        const float2* wlp = Wl2 + idx2;
#pragma unroll
        for (int b = 0; b < BB; b++) {
            const unsigned on0 = (g >> b) & 1u;
            const unsigned on1 = (g >> (8 + b)) & 1u;
            if (on0 | on1) {
                const float2 wl = wlp[(size_t)b * (NN2 / 2)];
                if (on0) acc0[b] += fmaf(cp0, wl.x, cs0);
                if (on1) acc1[b] += fmaf(cp1, wl.y, cs1);
            }
        }
    }

#pragma unroll
    for (int b = 0; b < BB; b++) {
        atomicAdd(&out[b * NN + o],     acc0[b]);
        atomicAdd(&out[b * NN + o + 1], acc1[b]);
    }
}

// ---------------------------------------------------------------------------
// Launch
// ---------------------------------------------------------------------------
extern "C" void kernel_launch(void* const* d_in, const int* in_sizes, int n_in,
                              void* d_out, int out_size) {
    const float* Xd = (const float*)d_in[0];   // (D,B,N)
    const float* dm = (const float*)d_in[1];   // (D,N,N)
    const float* W  = (const float*)d_in[2];   // (N,N)
    const float* Wl = (const float*)d_in[3];   // (B,N,N)
    const float* F  = (const float*)d_in[4];   // (N,N)
    const float* S  = (const float*)d_in[5];   // (N,N)
    float* out = (float*)d_out;                // (B,N)

    zero_kernel<<<(BB * NN + 255) / 256, 256>>>(out);
    pack_kernel<<<(DD * BB * NN + 255) / 256, 256>>>(Xd);
    gate_kernel<<<NQ / 256, 256>>>((const float4*)dm);

    dim3 grid((NN / 2) / 256, ESPLIT);
    reduce_kernel<<<grid, 256>>>((const float2*)W, (const float2*)Wl,
                                 (const float2*)F, (const float2*)S, out);
}

// round 6
// speedup vs baseline: 1.1215x; 1.0978x over previous
#include <cuda_runtime.h>
#include <cstdint>

#define DD 8
#define BB 8
#define NN 2048
#define NN2 (NN * NN)        // 4194304
#define NQ  (NN2 / 4)        // 1048576 quads

// 64-bit spike mask per presynaptic neuron e: bit (d*8 + b) set iff Xd[d,b,e]==1
__device__ unsigned long long g_spike[NN];
// Gate byte per synapse (e,o): bit b set iff Xd[didx(e,o), b, e]==1. Packed 4/word.
__device__ unsigned int g_gate[NQ];   // 4 MB static scratch

// ---------------------------------------------------------------------------
// Kernel 1: pack Xd (D,B,N) binary floats into per-e 64-bit masks (atomicOr;
// g_spike pre-zeroed by memset node).
// ---------------------------------------------------------------------------
__global__ void __launch_bounds__(256)
pack_kernel(const float* __restrict__ Xd) {
    int i = blockIdx.x * blockDim.x + threadIdx.x;  // over D*B*N
    if (i >= DD * BB * NN) return;
    if (Xd[i] > 0.5f) {
        int e  = i % NN;
        int db = i / NN;             // bit index = d*B + b
        atomicOr(&g_spike[e], 1ull << db);
    }
}

// ---------------------------------------------------------------------------
// Kernel 2: stream delaymap -> gate bytes. d=0 plane never read (contributes
// 0 to the one-hot dot product). Pure streaming, 4096 CTAs. ~Roofline.
// ---------------------------------------------------------------------------
__global__ void __launch_bounds__(256)
gate_kernel(const float4* __restrict__ dm4) {
    int i = blockIdx.x * blockDim.x + threadIdx.x;  // quad index over N*N/4
    if (i >= NQ) return;
    const int e = i / (NN / 4);                     // warp-uniform row

    float fx = 0.f, fy = 0.f, fz = 0.f, fw = 0.f;
#pragma unroll
    for (int d = 1; d < DD; d++) {
        float4 v = dm4[(size_t)d * NQ + i];
        const float fd = (float)d;
        fx = fmaf(v.x, fd, fx);
        fy = fmaf(v.y, fd, fy);
        fz = fmaf(v.z, fd, fz);
        fw = fmaf(v.w, fd, fw);
    }
    const unsigned long long bits = g_spike[e];
    unsigned b0 = (unsigned)(bits >> (((int)fx) * 8)) & 0xFFu;
    unsigned b1 = (unsigned)(bits >> (((int)fy) * 8)) & 0xFFu;
    unsigned b2 = (unsigned)(bits >> (((int)fz) * 8)) & 0xFFu;
    unsigned b3 = (unsigned)(bits >> (((int)fw) * 8)) & 0xFFu;
    g_gate[i] = b0 | (b1 << 8) | (b2 << 16) | (b3 << 24);
}

// ---------------------------------------------------------------------------
// Kernel 3: gated blend + reduce. R3 skeleton + register gate prefetch +
// batched predicated Wlong loads (load phase separated from FMA phase).
// thread -> o; block.y -> chunk of e. 1024 CTAs.
// ---------------------------------------------------------------------------
#define ESPLIT 128
#define ECHUNK (NN / ESPLIT)   // 16

__global__ void __launch_bounds__(256)
reduce_kernel(const float* __restrict__ W,     // (N,N)
              const float* __restrict__ Wl,    // Wlong (B,N,N)
              const float* __restrict__ F,     // STDP_frac (N,N)
              const float* __restrict__ S,     // signs (N,N)
              float* __restrict__ out)         // (B,N)
{
    const int o     = blockIdx.x * blockDim.x + threadIdx.x;
    const int ebase = blockIdx.y * ECHUNK;
    const unsigned char* __restrict__ gb8 = (const unsigned char*)g_gate;

    // Phase 0: prefetch all gate bytes for the chunk into registers.
    // 16 independent loads; branch predicates below are register-known.
    unsigned gb[ECHUNK];
#pragma unroll
    for (int ee = 0; ee < ECHUNK; ee++) {
        gb[ee] = gb8[(size_t)(ebase + ee) * NN + o];
    }

    float acc[BB];
#pragma unroll
    for (int b = 0; b < BB; b++) acc[b] = 0.0f;

#pragma unroll
    for (int ee = 0; ee < ECHUNK; ee++) {
        const unsigned g = gb[ee];
        if (g == 0) continue;                      // register branch: no mem stall

        const size_t eo = (size_t)(ebase + ee) * NN + o;
        const float s = S[eo];
        const float w = W[eo];
        const float f = F[eo];
        const float cs = s * w * (1.0f - f);       // static part
        const float cp = s * f;                    // plastic multiplier

        // Load phase: batch all gated Wlong loads (independent, MLP ~8)
        const float* wlp = Wl + eo;
        float wl[BB];
#pragma unroll
        for (int b = 0; b < BB; b++) {
            wl[b] = ((g >> b) & 1u) ? wlp[(size_t)b * NN2] : 0.0f;
        }
        // FMA phase: consumers issued after all loads are in flight
#pragma unroll
        for (int b = 0; b < BB; b++) {
            if ((g >> b) & 1u) acc[b] += fmaf(cp, wl[b], cs);
        }
    }

#pragma unroll
    for (int b = 0; b < BB; b++) {
        atomicAdd(&out[b * NN + o], acc[b]);
    }
}

// ---------------------------------------------------------------------------
// Launch
// ---------------------------------------------------------------------------
extern "C" void kernel_launch(void* const* d_in, const int* in_sizes, int n_in,
                              void* d_out, int out_size) {
    const float* Xd = (const float*)d_in[0];   // (D,B,N)
    const float* dm = (const float*)d_in[1];   // (D,N,N)
    const float* W  = (const float*)d_in[2];   // (N,N)
    const float* Wl = (const float*)d_in[3];   // (B,N,N)
    const float* F  = (const float*)d_in[4];   // (N,N)
    const float* S  = (const float*)d_in[5];   // (N,N)
    float* out = (float*)d_out;                // (B,N)

    // Memset nodes (graph-capturable): zero spike masks + output
    void* spike_addr = nullptr;
    cudaGetSymbolAddress(&spike_addr, g_spike);
    cudaMemsetAsync(spike_addr, 0, NN * sizeof(unsigned long long));
    cudaMemsetAsync(out, 0, BB * NN * sizeof(float));

    pack_kernel<<<(DD * BB * NN + 255) / 256, 256>>>(Xd);
    gate_kernel<<<NQ / 256, 256>>>((const float4*)dm);

    dim3 grid(NN / 256, ESPLIT);
    reduce_kernel<<<grid, 256>>>(W, Wl, F, S, out);
}

// round 7
// speedup vs baseline: 1.4184x; 1.2647x over previous
#include <cuda_runtime.h>
#include <cstdint>

#define DD 8
#define BB 8
#define NN 2048
#define NN2 (NN * NN)        // 4194304
#define NQ  (NN2 / 4)        // 1048576 quads (4 o's per quad)

// Gate byte per synapse (e,o): bit b set iff Xd[didx(e,o), b, e]==1. Packed 4/word.
__device__ unsigned int g_gate[NQ];   // 4 MB static scratch

// ---------------------------------------------------------------------------
// Kernel 1: gate kernel with in-CTA spike pack + active-plane skipping.
//   Each CTA (256 threads) covers 256 quads = half of one e-row
//   (512 quads/row)  =>  e = blockIdx.x >> 1  (warp/CTA-uniform).
//   Phase A: threads 0..63 load Xd[db, e], ballot into a 64-bit spike mask.
//   Phase B: for each delay d with nonzero batch mask, load the dm plane
//   quad and set the gate byte where the one-hot fires. Inactive planes are
//   never read (expected 2.7 of 8 planes) -> dm traffic ~45 MB instead of 134.
// ---------------------------------------------------------------------------
__global__ void __launch_bounds__(256)
gate_kernel(const float4* __restrict__ dm4, const float* __restrict__ Xd) {
    const int e = blockIdx.x >> 1;                       // one e per CTA
    const int i = blockIdx.x * 256 + threadIdx.x;        // quad index

    // Phase A: build 64-bit spike mask for this e (bit db = d*8+b)
    __shared__ unsigned sm_bits[2];
    if (threadIdx.x < 64) {
        const int db = threadIdx.x;
        const bool sp = Xd[(size_t)db * NN + e] > 0.5f;
        const unsigned bal = __ballot_sync(0xFFFFFFFFu, sp);
        if ((threadIdx.x & 31) == 0) sm_bits[threadIdx.x >> 5] = bal;
    }
    __syncthreads();
    const unsigned long long bits =
        (unsigned long long)sm_bits[0] | ((unsigned long long)sm_bits[1] << 32);

    // Phase B: read only active planes; one-hot picks the gate byte
    unsigned g0 = 0, g1 = 0, g2 = 0, g3 = 0;
#pragma unroll
    for (int d = 0; d < DD; d++) {
        const unsigned m8 = (unsigned)(bits >> (d * 8)) & 0xFFu;
        if (m8) {                                        // CTA-uniform branch
            const float4 v = dm4[(size_t)d * NQ + i];
            if (v.x > 0.5f) g0 = m8;
            if (v.y > 0.5f) g1 = m8;
            if (v.z > 0.5f) g2 = m8;
            if (v.w > 0.5f) g3 = m8;
        }
    }
    g_gate[i] = g0 | (g1 << 8) | (g2 << 16) | (g3 << 24);
}

// ---------------------------------------------------------------------------
// Kernel 2: gated blend + reduce. R3's proven branchy body, ESPLIT doubled.
//   thread -> o; block.y -> chunk of e. 2048 CTAs.
// ---------------------------------------------------------------------------
#define ESPLIT 256
#define ECHUNK (NN / ESPLIT)   // 8

__global__ void __launch_bounds__(256)
reduce_kernel(const float* __restrict__ W,     // (N,N)
              const float* __restrict__ Wl,    // Wlong (B,N,N)
              const float* __restrict__ F,     // STDP_frac (N,N)
              const float* __restrict__ S,     // signs (N,N)
              float* __restrict__ out)         // (B,N)
{
    const int o     = blockIdx.x * blockDim.x + threadIdx.x;
    const int ebase = blockIdx.y * ECHUNK;
    const unsigned char* __restrict__ gb8 = (const unsigned char*)g_gate;

    float acc[BB];
#pragma unroll
    for (int b = 0; b < BB; b++) acc[b] = 0.0f;

#pragma unroll 4
    for (int ee = 0; ee < ECHUNK; ee++) {
        const int e = ebase + ee;
        const size_t eo = (size_t)e * NN + o;
        const unsigned gb = gb8[eo];
        if (gb == 0) continue;

        const float s = S[eo];
        const float w = W[eo];
        const float f = F[eo];
        const float cs = s * w * (1.0f - f);   // static part
        const float cp = s * f;                // plastic multiplier

        const float* wlp = Wl + eo;
#pragma unroll
        for (int b = 0; b < BB; b++) {
            if (gb & (1u << b)) {
                acc[b] += cs + cp * wlp[(size_t)b * NN2];
            }
        }
    }

#pragma unroll
    for (int b = 0; b < BB; b++) {
        atomicAdd(&out[b * NN + o], acc[b]);
    }
}

// ---------------------------------------------------------------------------
// Launch
// ---------------------------------------------------------------------------
extern "C" void kernel_launch(void* const* d_in, const int* in_sizes, int n_in,
                              void* d_out, int out_size) {
    const float* Xd = (const float*)d_in[0];   // (D,B,N)
    const float* dm = (const float*)d_in[1];   // (D,N,N)
    const float* W  = (const float*)d_in[2];   // (N,N)
    const float* Wl = (const float*)d_in[3];   // (B,N,N)
    const float* F  = (const float*)d_in[4];   // (N,N)
    const float* S  = (const float*)d_in[5];   // (N,N)
    float* out = (float*)d_out;                // (B,N)

    cudaMemsetAsync(out, 0, BB * NN * sizeof(float));

    gate_kernel<<<NQ / 256, 256>>>((const float4*)dm, Xd);

    dim3 grid(NN / 256, ESPLIT);
    reduce_kernel<<<grid, 256>>>(W, Wl, F, S, out);
}

// round 8
// speedup vs baseline: 1.5370x; 1.0836x over previous
#include <cuda_runtime.h>
#include <cstdint>

#define DD 8
#define BB 8
#define NN 2048
#define NN2 (NN * NN)        // 4194304
#define NQ  (NN2 / 4)        // 1048576 quads (4 o's per quad)

// Gate byte per synapse (e,o): bit b set iff Xd[didx(e,o), b, e]==1. Packed 4/word.
__device__ unsigned int g_gate[NQ];   // 4 MB static scratch

// ---------------------------------------------------------------------------
// Kernel 1: gate kernel with in-CTA spike pack + active-plane skipping.
//   One CTA per e-row (512 quads); each thread handles 2 quads -> 2x MLP.
//   Phase A: threads 0..63 load Xd[db, e], ballot into 64-bit spike mask.
//   Phase B: only planes d with a spike in some batch are read (E~2.7/8),
//   cutting delaymap traffic 134 MB -> ~45 MB. One-hot => gate byte = m8(d).
// ---------------------------------------------------------------------------
__global__ void __launch_bounds__(256)
gate_kernel(const float4* __restrict__ dm4, const float* __restrict__ Xd) {
    const int e  = blockIdx.x;                        // one e per CTA
    const int i0 = e * 512 + threadIdx.x;             // first quad
    const int i1 = i0 + 256;                          // second quad

    __shared__ unsigned sm_bits[2];
    if (threadIdx.x < 64) {
        const bool sp = Xd[(size_t)threadIdx.x * NN + e] > 0.5f;
        const unsigned bal = __ballot_sync(0xFFFFFFFFu, sp);
        if ((threadIdx.x & 31) == 0) sm_bits[threadIdx.x >> 5] = bal;
    }
    __syncthreads();
    const unsigned long long bits =
        (unsigned long long)sm_bits[0] | ((unsigned long long)sm_bits[1] << 32);

    unsigned a0 = 0, a1 = 0, a2 = 0, a3 = 0;   // gate bytes, quad 0
    unsigned b0 = 0, b1 = 0, b2 = 0, b3 = 0;   // gate bytes, quad 1
#pragma unroll
    for (int d = 0; d < DD; d++) {
        const unsigned m8 = (unsigned)(bits >> (d * 8)) & 0xFFu;
        if (m8) {                                     // CTA-uniform branch
            const float4 u = dm4[(size_t)d * NQ + i0];
            const float4 v = dm4[(size_t)d * NQ + i1];
            if (u.x > 0.5f) a0 = m8;
            if (u.y > 0.5f) a1 = m8;
            if (u.z > 0.5f) a2 = m8;
            if (u.w > 0.5f) a3 = m8;
            if (v.x > 0.5f) b0 = m8;
            if (v.y > 0.5f) b1 = m8;
            if (v.z > 0.5f) b2 = m8;
            if (v.w > 0.5f) b3 = m8;
        }
    }
    g_gate[i0] = a0 | (a1 << 8) | (a2 << 16) | (a3 << 24);
    g_gate[i1] = b0 | (b1 << 8) | (b2 << 16) | (b3 << 24);
}

// ---------------------------------------------------------------------------
// Kernel 2: gated blend + reduce, thread -> (o, b).
//   Block = 256 threads = 8 warps; warp w handles batch b=w over the SAME
//   32 consecutive o. One accumulator per thread; all loads per iteration
//   independent -> deep MLP. Wlong coalesced within plane b; fully
//   predicated-off when (e,b) had no spike. Statics/gates L1-shared by warps.
// ---------------------------------------------------------------------------
#define ESPLIT 64
#define ECHUNK (NN / ESPLIT)   // 32

__global__ void __launch_bounds__(256)
reduce_kernel(const float* __restrict__ W,     // (N,N)
              const float* __restrict__ Wl,    // Wlong (B,N,N)
              const float* __restrict__ F,     // STDP_frac (N,N)
              const float* __restrict__ S,     // signs (N,N)
              float* __restrict__ out)         // (B,N)
{
    const int lane  = threadIdx.x & 31;
    const int b     = threadIdx.x >> 5;          // warp index = batch
    const int o     = blockIdx.x * 32 + lane;
    const int ebase = blockIdx.y * ECHUNK;
    const unsigned char* __restrict__ gb8 = (const unsigned char*)g_gate;
    const float* __restrict__ wlb = Wl + (size_t)b * NN2;

    float acc = 0.0f;
    size_t eo = (size_t)ebase * NN + o;
#pragma unroll 8
    for (int ee = 0; ee < ECHUNK; ee++, eo += NN) {
        const unsigned g = gb8[eo];
        const bool on = (g >> b) & 1u;
        const float s = S[eo];                  // L1 hit for 7/8 warps
        const float w = W[eo];
        const float f = F[eo];
        const float wl = on ? wlb[eo] : 0.0f;   // @P LDG, coalesced in plane b
        if (on) acc += s * fmaf(f, wl - w, w);  // s*(w*(1-f)+wl*f)
    }

    atomicAdd(&out[b * NN + o], acc);
}

// ---------------------------------------------------------------------------
// Launch
// ---------------------------------------------------------------------------
extern "C" void kernel_launch(void* const* d_in, const int* in_sizes, int n_in,
                              void* d_out, int out_size) {
    const float* Xd = (const float*)d_in[0];   // (D,B,N)
    const float* dm = (const float*)d_in[1];   // (D,N,N)
    const float* W  = (const float*)d_in[2];   // (N,N)
    const float* Wl = (const float*)d_in[3];   // (B,N,N)
    const float* F  = (const float*)d_in[4];   // (N,N)
    const float* S  = (const float*)d_in[5];   // (N,N)
    float* out = (float*)d_out;                // (B,N)

    cudaMemsetAsync(out, 0, BB * NN * sizeof(float));

    gate_kernel<<<NN, 256>>>((const float4*)dm, Xd);

    dim3 grid(NN / 32, ESPLIT);
    reduce_kernel<<<grid, 256>>>(W, Wl, F, S, out);
}